// round 15
// baseline (speedup 1.0000x reference)
#include <cuda_runtime.h>
#include <cuda_fp16.h>
#include <cstdint>
#include <cstddef>

#define NTOK 8192
#define IN_DIM 1024
#define HID_DIM 4096
#define OUT_DIM 1024
#define NE 8
#define NKT1 (IN_DIM / 32)   // 32-k chunks (packing granularity)
#define NKT2 (HID_DIM / 32)

// Packed tile buffers (uint4 units; per 32-k chunk: A-tile 128x32h = 8KB = 512 u4,
// B-tile 256x32h = 16KB = 1024 u4; 128-row halves of B chunks are contiguous 8KB spans).
__device__ uint4 g_xp[(size_t)64 * NKT1 * 512];            // x packed: (mb, kt) 16MB
__device__ uint4 g_hp[(size_t)NE * 64 * NKT2 * 512];       // h packed: (e*64+mb, kt) 512MB
__device__ uint4 g_w1p[(size_t)NE * 16 * NKT1 * 1024];     // W1^T packed: (e,nb,kt) 64MB
__device__ uint4 g_w2p[(size_t)NE * 4 * NKT2 * 1024];      // W2^T packed 64MB
__device__ __half g_hh[(size_t)NE * NTOK * HID_DIM];       // GEMM1 out, row-major
__device__ __half g_yh[(size_t)NE * NTOK * OUT_DIM];       // GEMM2 out, row-major
// fp16 gamma/beta (exactly representable: ones/zeros)
__device__ __half g_g1h[(size_t)NE * HID_DIM];
__device__ __half g_b1h[(size_t)NE * HID_DIM];
__device__ __half g_g2h[(size_t)NE * OUT_DIM];
__device__ __half g_b2h[(size_t)NE * OUT_DIM];

// ---------------- helpers ----------------
__device__ __forceinline__ float geluf(float x) {
    return 0.5f * x * (1.0f + erff(x * 0.70710678118654752f));
}
__device__ __forceinline__ uint32_t smem_u32(const void* p) {
    uint32_t a;
    asm("{ .reg .u64 t; cvta.to.shared.u64 t, %1; cvt.u32.u64 %0, t; }" : "=r"(a) : "l"(p));
    return a;
}
__device__ __forceinline__ uint4 pack8h(const float* v) {
    uint4 u;
    __half2 a = __floats2half2_rn(v[0], v[1]);
    __half2 b = __floats2half2_rn(v[2], v[3]);
    __half2 c = __floats2half2_rn(v[4], v[5]);
    __half2 d = __floats2half2_rn(v[6], v[7]);
    u.x = *(uint32_t*)&a; u.y = *(uint32_t*)&b;
    u.z = *(uint32_t*)&c; u.w = *(uint32_t*)&d;
    return u;
}
__device__ __forceinline__ void bulkcp(uint32_t dst, const void* src, uint32_t bytes, uint32_t mbar) {
    asm volatile(
        "cp.async.bulk.shared::cluster.global.mbarrier::complete_tx::bytes [%0], [%1], %2, [%3];"
        :: "r"(dst), "l"(src), "r"(bytes), "r"(mbar) : "memory");
}

#define MBAR_INIT(addr, cnt) \
    asm volatile("mbarrier.init.shared.b64 [%0], %1;" :: "r"(addr), "r"((uint32_t)(cnt)) : "memory")
#define MBAR_EXPECT(addr, n) \
    asm volatile("mbarrier.arrive.expect_tx.shared.b64 _, [%0], %1;" :: "r"(addr), "r"((uint32_t)(n)) : "memory")
#define MBAR_ARRIVE(addr) \
    asm volatile("mbarrier.arrive.shared.b64 _, [%0];" :: "r"(addr) : "memory")
#define MBAR_WAIT(addr, parity) do {                                              \
    uint32_t _m = (addr); uint32_t _p = (parity); uint32_t _d;                    \
    asm volatile("{\n\t.reg .pred p;\n\t"                                         \
        "mbarrier.try_wait.parity.acquire.cta.shared::cta.b64 p, [%1], %2;\n\t"   \
        "selp.b32 %0, 1, 0, p;\n\t}"                                              \
        : "=r"(_d) : "r"(_m), "r"(_p) : "memory");                                \
    if (!_d) {                                                                    \
        asm volatile("{\n\t.reg .pred P1;\n\t"                                    \
            "WAIT_LOOP_%=:\n\t"                                                   \
            "mbarrier.try_wait.parity.acquire.cta.shared::cta.b64 P1, [%0], %1, 0x989680;\n\t" \
            "@P1 bra.uni WAIT_DONE_%=;\n\t"                                       \
            "bra.uni WAIT_LOOP_%=;\n\t"                                           \
            "WAIT_DONE_%=:\n\t}"                                                  \
            :: "r"(_m), "r"(_p) : "memory");                                      \
    }                                                                             \
} while (0)

#define LDM4(r, addr)                                                            \
    asm volatile("ldmatrix.sync.aligned.m8n8.x4.shared.b16 {%0,%1,%2,%3}, [%4];" \
                 : "=r"((r)[0]), "=r"((r)[1]), "=r"((r)[2]), "=r"((r)[3])        \
                 : "r"(addr))

#define MMA16816(c, a, b0, b1)                                                   \
    asm volatile("mma.sync.aligned.m16n8k16.row.col.f32.f16.f16.f32 "            \
                 "{%0,%1,%2,%3}, {%4,%5,%6,%7}, {%8,%9}, {%0,%1,%2,%3};"         \
                 : "+f"((c)[0]), "+f"((c)[1]), "+f"((c)[2]), "+f"((c)[3])        \
                 : "r"((a)[0]), "r"((a)[1]), "r"((a)[2]), "r"((a)[3]),           \
                   "r"(b0), "r"(b1))

// ---------------- bulk-copy GEMM: C[e] = A @ Bt[e]^T + bias[e], fp16 out ----------------
// CTA 128x128, 256 threads (8 warps, 4M x 2N), warp tile 32x64. 2 CTAs/SM.
// 32-k pipeline stages (A 8KB + B 8KB), 4-deep mbarrier ring; no syncthreads in loop.
// B fragments register-double-buffered across the 2 k16 halves of each stage.
#define A_T 8192
#define B_T 8192
#define STG (A_T + B_T)             // 16384
#define NST 4
#define SMEM_GEMM (256 + NST * STG) // 65792

template <bool FIRST>
__global__ void __launch_bounds__(256, 2) gemm_b(
    const uint4* __restrict__ Ap, const uint4* __restrict__ Bp,
    const float* __restrict__ bias, __half* __restrict__ C, const int ebase) {
    constexpr int KDIM = FIRST ? IN_DIM : HID_DIM;
    constexpr int NDIM = FIRST ? HID_DIM : OUT_DIM;
    constexpr int NKT = KDIM / 32;   // 32-k stages

    extern __shared__ char smem[];
    const uint32_t sb = smem_u32(smem);
    const uint32_t FULLB = sb, EMPTYB = sb + 64, TILES = sb + 256;

    const int tid = threadIdx.x, lane = tid & 31, wid = tid >> 5;
    const int mb = blockIdx.x, nb = blockIdx.y;
    const int e = ebase + blockIdx.z;

    if (tid == 0) {
#pragma unroll
        for (int s = 0; s < NST; s++) { MBAR_INIT(FULLB + 8 * s, 1); MBAR_INIT(EMPTYB + 8 * s, 8); }
    }
    __syncthreads();

    const uint4* Asrc = Ap + (size_t)(FIRST ? mb : (e * 64 + mb)) * NKT * 512;
    // 128-row half of the 256-row packed B chunk: contiguous 8KB at + (nb&1)*512 u4
    const uint4* Bsrc = Bp + (size_t)(e * (NDIM / 256) + (nb >> 1)) * NKT * 1024
                        + (size_t)(nb & 1) * 512;

    auto fill = [&](int c) {
        const int s = c & (NST - 1);
        if (c >= NST) MBAR_WAIT(EMPTYB + 8 * s, (uint32_t)(((c / NST) - 1) & 1));
        MBAR_EXPECT(FULLB + 8 * s, STG);
        bulkcp(TILES + s * STG,       Asrc + (size_t)c * 512,  A_T, FULLB + 8 * s);
        bulkcp(TILES + s * STG + A_T, Bsrc + (size_t)c * 1024, B_T, FULLB + 8 * s);
    };

    if (tid == 0) { fill(0); fill(1); fill(2); }

    // fragment addressing (swizzle: quad ^= (row>>1)&3, rows are 64B within each 32-k chunk)
    const int wm = (wid >> 1) * 32, wn = (wid & 1) * 64;
    uint32_t aOff[2], aXs[2], bOff[4], bXs[4];
#pragma unroll
    for (int i = 0; i < 2; i++) {
        const int r = wm + (lane & 15) + 16 * i;
        aOff[i] = (uint32_t)(r * 64);
        aXs[i] = (uint32_t)(((r >> 1) & 3) << 4);
    }
#pragma unroll
    for (int t = 0; t < 4; t++) {
        const int r = wn + (lane & 15) + 16 * t;
        bOff[t] = (uint32_t)(r * 64);
        bXs[t] = (uint32_t)(((r >> 1) & 3) << 4);
    }
    const uint32_t qb = (uint32_t)((lane >> 4) << 4);

    float acc[2][8][4];
#pragma unroll
    for (int i = 0; i < 2; i++)
#pragma unroll
        for (int j = 0; j < 8; j++)
#pragma unroll
            for (int r = 0; r < 4; r++) acc[i][j][r] = 0.0f;

    uint32_t af[2][4], brA[4][4], brB[4][4];

    for (int kt = 0; kt < NKT; kt++) {
        if (tid == 0 && kt + NST - 1 < NKT) fill(kt + NST - 1);
        MBAR_WAIT(FULLB + 8 * (kt & (NST - 1)), (uint32_t)((kt / NST) & 1));
        const uint32_t st = TILES + (uint32_t)(kt & (NST - 1)) * STG;

        // preload B frags for k16 half 0
#pragma unroll
        for (int t = 0; t < 4; t++) LDM4(brA[t], st + A_T + bOff[t] + (qb ^ bXs[t]));

        // half 0: A frags, prefetch half-1 B frags, MMA with brA
#pragma unroll
        for (int i = 0; i < 2; i++) LDM4(af[i], st + aOff[i] + (qb ^ aXs[i]));
#pragma unroll
        for (int t = 0; t < 4; t++) LDM4(brB[t], st + A_T + bOff[t] + ((qb + 32) ^ bXs[t]));
#pragma unroll
        for (int i = 0; i < 2; i++)
#pragma unroll
            for (int j = 0; j < 8; j++) {
                const int t = j >> 1;
                const uint32_t b0 = (j & 1) ? brA[t][1] : brA[t][0];
                const uint32_t b1 = (j & 1) ? brA[t][3] : brA[t][2];
                MMA16816(acc[i][j], af[i], b0, b1);
            }

        // half 1: A frags, MMA with brB
#pragma unroll
        for (int i = 0; i < 2; i++) LDM4(af[i], st + aOff[i] + ((qb + 32) ^ aXs[i]));
#pragma unroll
        for (int i = 0; i < 2; i++)
#pragma unroll
            for (int j = 0; j < 8; j++) {
                const int t = j >> 1;
                const uint32_t b0 = (j & 1) ? brB[t][1] : brB[t][0];
                const uint32_t b1 = (j & 1) ? brB[t][3] : brB[t][2];
                MMA16816(acc[i][j], af[i], b0, b1);
            }

        __syncwarp();
        if (lane == 0) MBAR_ARRIVE(EMPTYB + 8 * (kt & (NST - 1)));
    }

    // epilogue: bias add, fp16 store (row-major C)
    __half* Ce = C + (size_t)e * NTOK * NDIM;
    const int m0 = mb * 128, n0 = nb * 128;
    const int g = lane >> 2, tg = lane & 3;
#pragma unroll
    for (int i = 0; i < 2; i++) {
        const int row = m0 + wm + i * 16 + g;
#pragma unroll
        for (int j = 0; j < 8; j++) {
            const int col = n0 + wn + j * 8 + tg * 2;
            const float bv0 = bias[(size_t)e * NDIM + col];
            const float bv1 = bias[(size_t)e * NDIM + col + 1];
            *(__half2*)(Ce + (size_t)row * NDIM + col) =
                __floats2half2_rn(acc[i][j][0] + bv0, acc[i][j][1] + bv1);
            *(__half2*)(Ce + (size_t)(row + 8) * NDIM + col) =
                __floats2half2_rn(acc[i][j][2] + bv0, acc[i][j][3] + bv1);
        }
    }
}

// ---------------- weight pack: W [E][K][N] fp32 -> packed fp16 B-tiles ----------------
template <bool W1SEL>
__global__ void __launch_bounds__(256) pack_w(const float* __restrict__ W, int K, int N,
                                              const int ebase) {
    __shared__ __half sm[256][34];
    const int e = ebase + blockIdx.z, nb = blockIdx.x, kt = blockIdx.y;
    const int tid = threadIdx.x;
    const float* ip = W + ((size_t)e * K + (size_t)kt * 32) * N + (size_t)nb * 256;
#pragma unroll
    for (int kk = 0; kk < 32; kk++)
        sm[tid][kk] = __float2half_rn(ip[(size_t)kk * N + tid]);
    __syncthreads();
    uint4* op = W1SEL ? g_w1p : g_w2p;
    const size_t tb = ((size_t)(e * (N / 256) + nb) * (K / 32) + kt) * 1024;
    const uint32_t xr = (uint32_t)((tid >> 1) & 3);
#pragma unroll
    for (int q = 0; q < 4; q++) {
        uint4 u;
        const __half2* s2 = (const __half2*)&sm[tid][q * 8];
        u.x = *(const uint32_t*)&s2[0]; u.y = *(const uint32_t*)&s2[1];
        u.z = *(const uint32_t*)&s2[2]; u.w = *(const uint32_t*)&s2[3];
        op[tb + (size_t)tid * 4 + ((uint32_t)q ^ xr)] = u;
    }
}

// ---------------- x pack: fp32 [8192,1024] -> packed fp16 A-tiles ----------------
__global__ void __launch_bounds__(256) pack_x(const float* __restrict__ x) {
    const int mb = blockIdx.x, kt = blockIdx.y, tid = threadIdx.x;
    const int r = tid >> 1, h16 = tid & 1;
    const float* ip = x + (size_t)(mb * 128 + r) * 1024 + kt * 32 + h16 * 16;
    float v[16];
    *(float4*)(v)      = *(const float4*)(ip);
    *(float4*)(v + 4)  = *(const float4*)(ip + 4);
    *(float4*)(v + 8)  = *(const float4*)(ip + 8);
    *(float4*)(v + 12) = *(const float4*)(ip + 12);
    const size_t tb = ((size_t)mb * NKT1 + kt) * 512;
    const uint32_t xr = (uint32_t)((r >> 1) & 3);
    const uint32_t q0 = (uint32_t)(h16 * 2);
    g_xp[tb + (size_t)r * 4 + (q0 ^ xr)]       = pack8h(v);
    g_xp[tb + (size_t)r * 4 + ((q0 + 1) ^ xr)] = pack8h(v + 8);
}

// ---------------- fp32 -> fp16 convert (gamma/beta) ----------------
__global__ void conv_h(const float* __restrict__ src, __half* __restrict__ dst) {
    const int i = (blockIdx.x * 256 + threadIdx.x) * 4;
    float4 v = *(const float4*)(src + i);
    __half2* o = (__half2*)(dst + i);
    o[0] = __floats2half2_rn(v.x, v.y);
    o[1] = __floats2half2_rn(v.z, v.w);
}

// ------- LayerNorm + GELU: g_hh row-major -> g_hp packed A-tiles (per expert) -------
__global__ void __launch_bounds__(256) ln_gelu_kernel(const int e) {
    __shared__ float red[16];
    const int m = blockIdx.x;
    const __half* p = g_hh + ((size_t)e * NTOK + m) * HID_DIM;
    const int tid = threadIdx.x;

    float vals[16];
    float s = 0.f, s2 = 0.f;
    const __half2* ph = (const __half2*)(p + tid * 16);
#pragma unroll
    for (int i = 0; i < 8; i++) {
        float2 f = __half22float2(ph[i]);
        vals[2 * i] = f.x; vals[2 * i + 1] = f.y;
        s += f.x + f.y;
        s2 += f.x * f.x + f.y * f.y;
    }
#pragma unroll
    for (int o = 16; o > 0; o >>= 1) {
        s  += __shfl_xor_sync(0xffffffffu, s, o);
        s2 += __shfl_xor_sync(0xffffffffu, s2, o);
    }
    const int wi = tid >> 5, ln = tid & 31;
    if (ln == 0) { red[wi] = s; red[8 + wi] = s2; }
    __syncthreads();
    if (tid == 0) {
        float ts = 0.f, t2 = 0.f;
        for (int k = 0; k < 8; k++) { ts += red[k]; t2 += red[8 + k]; }
        red[0] = ts; red[8] = t2;
    }
    __syncthreads();
    const float invL = 1.0f / (float)HID_DIM;
    const float mean = red[0] * invL;
    const float inv = rsqrtf(red[8] * invL - mean * mean + 1e-5f);
    const __half2* gmp = (const __half2*)(g_g1h + (size_t)e * HID_DIM + tid * 16);
    const __half2* btp = (const __half2*)(g_b1h + (size_t)e * HID_DIM + tid * 16);
#pragma unroll
    for (int i = 0; i < 8; i++) {
        float2 gv = __half22float2(gmp[i]);
        float2 bv = __half22float2(btp[i]);
        vals[2 * i]     = geluf((vals[2 * i]     - mean) * inv * gv.x + bv.x);
        vals[2 * i + 1] = geluf((vals[2 * i + 1] - mean) * inv * gv.y + bv.y);
    }

    const int mb = m >> 7, r = m & 127, kt = tid >> 1;
    const uint32_t q0 = (uint32_t)((tid & 1) * 2);
    const uint32_t xr = (uint32_t)((r >> 1) & 3);
    const size_t tb = ((size_t)(e * 64 + mb) * NKT2 + kt) * 512;
    g_hp[tb + (size_t)r * 4 + (q0 ^ xr)]       = pack8h(vals);
    g_hp[tb + (size_t)r * 4 + ((q0 + 1) ^ xr)] = pack8h(vals + 8);
}

// -------- Final (4-expert half): LN(OUT) + GELU, weighted accumulate into out --------
__global__ void __launch_bounds__(256) final_kernel(
    const float* __restrict__ weights, float* __restrict__ out, const int ebase) {
    __shared__ float red[16];
    const int b = blockIdx.x;
    const int tid = threadIdx.x;
    const int wi = tid >> 5, ln = tid & 31;

    float accv[4] = {0.f, 0.f, 0.f, 0.f};
#pragma unroll 1
    for (int ee = 0; ee < 4; ee++) {
        const int e = ebase + ee;
        const __half* p = g_yh + ((size_t)e * NTOK + b) * OUT_DIM;
        float vals[4];
        float s = 0.f, s2 = 0.f;
#pragma unroll
        for (int r = 0; r < 4; r++) {
            float v = __half2float(p[tid + r * 256]);
            vals[r] = v;
            s += v; s2 += v * v;
        }
#pragma unroll
        for (int o = 16; o > 0; o >>= 1) {
            s  += __shfl_xor_sync(0xffffffffu, s, o);
            s2 += __shfl_xor_sync(0xffffffffu, s2, o);
        }
        if (ln == 0) { red[wi] = s; red[8 + wi] = s2; }
        __syncthreads();
        if (tid == 0) {
            float ts = 0.f, t2 = 0.f;
            for (int k = 0; k < 8; k++) { ts += red[k]; t2 += red[8 + k]; }
            red[0] = ts; red[8] = t2;
        }
        __syncthreads();
        const float invL = 1.0f / (float)OUT_DIM;
        const float mean = red[0] * invL;
        const float inv = rsqrtf(red[8] * invL - mean * mean + 1e-5f);
        const float w = weights[(size_t)b * NE + e];
#pragma unroll
        for (int r = 0; r < 4; r++) {
            const int i = tid + r * 256;
            const float gv = __half2float(g_g2h[(size_t)e * OUT_DIM + i]);
            const float bv = __half2float(g_b2h[(size_t)e * OUT_DIM + i]);
            const float v = (vals[r] - mean) * inv * gv + bv;
            accv[r] += w * geluf(v);
        }
        __syncthreads();
    }
#pragma unroll
    for (int r = 0; r < 4; r++) {
        const size_t oi = (size_t)b * OUT_DIM + tid + r * 256;
        out[oi] = (ebase == 0) ? accv[r] : (out[oi] + accv[r]);
    }
}

// ---------------- launch: three-stream fork/join pipeline (capture-safe) ----------------
extern "C" void kernel_launch(void* const* d_in, const int* in_sizes, int n_in,
                              void* d_out, int out_size) {
    const float* x   = (const float*)d_in[0];
    const float* wts = (const float*)d_in[1];
    const float* W1  = (const float*)d_in[2];
    const float* b1  = (const float*)d_in[3];
    const float* g1  = (const float*)d_in[4];
    const float* be1 = (const float*)d_in[5];
    const float* W2  = (const float*)d_in[6];
    const float* b2  = (const float*)d_in[7];
    const float* g2  = (const float*)d_in[8];
    const float* be2 = (const float*)d_in[9];
    float* out = (float*)d_out;

    cudaFuncSetAttribute(gemm_b<true>,  cudaFuncAttributeMaxDynamicSharedMemorySize, SMEM_GEMM);
    cudaFuncSetAttribute(gemm_b<false>, cudaFuncAttributeMaxDynamicSharedMemorySize, SMEM_GEMM);

    uint4* xp;  cudaGetSymbolAddress((void**)&xp,  g_xp);
    uint4* hp;  cudaGetSymbolAddress((void**)&hp,  g_hp);
    uint4* w1p; cudaGetSymbolAddress((void**)&w1p, g_w1p);
    uint4* w2p; cudaGetSymbolAddress((void**)&w2p, g_w2p);
    __half* hh; cudaGetSymbolAddress((void**)&hh,  g_hh);
    __half* yh; cudaGetSymbolAddress((void**)&yh,  g_yh);
    __half* g1h; cudaGetSymbolAddress((void**)&g1h, g_g1h);
    __half* b1h; cudaGetSymbolAddress((void**)&b1h, g_b1h);
    __half* g2h; cudaGetSymbolAddress((void**)&g2h, g_g2h);
    __half* b2h; cudaGetSymbolAddress((void**)&b2h, g_b2h);

    const cudaStream_t s0 = 0;
    static cudaStream_t s1 = nullptr, s2 = nullptr;
    if (!s1) {
        cudaStreamCreateWithFlags(&s1, cudaStreamNonBlocking);
        cudaStreamCreateWithFlags(&s2, cudaStreamNonBlocking);
    }
    auto mkev = []() {
        cudaEvent_t ev;
        cudaEventCreateWithFlags(&ev, cudaEventDisableTiming);
        return ev;
    };
    cudaEvent_t evFork = mkev(), evJoin1 = mkev(), evJoin2 = mkev();
    cudaEvent_t evPW1 = mkev(), evG2a = mkev(), evG2b = mkev();
    cudaEvent_t evG1[NE], evLN[NE];
    for (int e = 0; e < NE; e++) { evG1[e] = mkev(); evLN[e] = mkev(); }

    // fork s1, s2 from the default stream
    cudaEventRecord(evFork, s0);
    cudaStreamWaitEvent(s1, evFork, 0);
    cudaStreamWaitEvent(s2, evFork, 0);

    // s0 critical path: only what GEMM1(0) needs
    pack_x<<<dim3(64, NKT1), 256, 0, s0>>>(x);
    pack_w<true><<<dim3(HID_DIM / 256, NKT1, 1), 256, 0, s0>>>(W1, IN_DIM, HID_DIM, 0);

    // s1: the rest of prep
    pack_w<true><<<dim3(HID_DIM / 256, NKT1, NE - 1), 256, 0, s1>>>(W1, IN_DIM, HID_DIM, 1);
    cudaEventRecord(evPW1, s1);
    conv_h<<<(NE * HID_DIM) / 1024, 256, 0, s1>>>(g1, g1h);
    conv_h<<<(NE * HID_DIM) / 1024, 256, 0, s1>>>(be1, b1h);
    pack_w<false><<<dim3(OUT_DIM / 256, NKT2, NE), 256, 0, s1>>>(W2, HID_DIM, OUT_DIM, 0);
    conv_h<<<(NE * OUT_DIM) / 1024, 256, 0, s1>>>(g2, g2h);
    conv_h<<<(NE * OUT_DIM) / 1024, 256, 0, s1>>>(be2, b2h);

    // phase 1: GEMM1 per expert on s0; LN per expert on s1 overlapped with next GEMM1
    for (int e = 0; e < NE; e++) {
        if (e == 1) cudaStreamWaitEvent(s0, evPW1, 0);  // experts 1..7 packed on s1
        gemm_b<true><<<dim3(64, HID_DIM / 128, 1), 256, SMEM_GEMM, s0>>>(xp, w1p, b1, hh, e);
        cudaEventRecord(evG1[e], s0);
        cudaStreamWaitEvent(s1, evG1[e], 0);
        ln_gelu_kernel<<<NTOK, 256, 0, s1>>>(e);
        cudaEventRecord(evLN[e], s1);
    }

    // phase 2 on s2: GEMM2 halves start as soon as their LNs are done,
    // overlapping GEMM1(4..7) still running on s0.
    for (int e = 0; e < 4; e++) cudaStreamWaitEvent(s2, evLN[e], 0);
    gemm_b<false><<<dim3(64, OUT_DIM / 128, 4), 256, SMEM_GEMM, s2>>>(hp, w2p, b2, yh, 0);
    cudaEventRecord(evG2a, s2);
    for (int e = 4; e < NE; e++) cudaStreamWaitEvent(s2, evLN[e], 0);
    gemm_b<false><<<dim3(64, OUT_DIM / 128, 4), 256, SMEM_GEMM, s2>>>(hp, w2p, b2, yh, 4);
    cudaEventRecord(evG2b, s2);

    // final halves on s1 (in-stream order preserves out accumulate ordering)
    cudaStreamWaitEvent(s1, evG2a, 0);
    final_kernel<<<NTOK, 256, 0, s1>>>(wts, out, 0);
    cudaStreamWaitEvent(s1, evG2b, 0);
    final_kernel<<<NTOK, 256, 0, s1>>>(wts, out, 4);

    // join both side streams back into the default stream
    cudaEventRecord(evJoin1, s1);
    cudaEventRecord(evJoin2, s2);
    cudaStreamWaitEvent(s0, evJoin1, 0);
    cudaStreamWaitEvent(s0, evJoin2, 0);
}

// round 16
// speedup vs baseline: 1.0184x; 1.0184x over previous
#include <cuda_runtime.h>
#include <cuda_fp16.h>
#include <cstdint>
#include <cstddef>

#define NTOK 8192
#define IN_DIM 1024
#define HID_DIM 4096
#define OUT_DIM 1024
#define NE 8
#define NKT1 (IN_DIM / 32)   // 32-k chunks (packing granularity)
#define NKT2 (HID_DIM / 32)

// Packed tile buffers (uint4 units; per 32-k chunk: A-tile 128x32h = 8KB = 512 u4,
// B-tile 256x32h = 16KB = 1024 u4).
__device__ uint4 g_xp[(size_t)64 * NKT1 * 512];            // x packed: (mb, kt) 16MB
__device__ uint4 g_hp[(size_t)NE * 64 * NKT2 * 512];       // h packed: (e*64+mb, kt) 512MB
__device__ uint4 g_w1p[(size_t)NE * 16 * NKT1 * 1024];     // W1^T packed: (e,nb,kt) 64MB
__device__ uint4 g_w2p[(size_t)NE * 4 * NKT2 * 1024];      // W2^T packed 64MB
__device__ __half g_hh[(size_t)NE * NTOK * HID_DIM];       // GEMM1 out, row-major
__device__ __half g_yh[(size_t)NE * NTOK * OUT_DIM];       // GEMM2 out, row-major
// fp16 gamma/beta (exactly representable: ones/zeros)
__device__ __half g_g1h[(size_t)NE * HID_DIM];
__device__ __half g_b1h[(size_t)NE * HID_DIM];
__device__ __half g_g2h[(size_t)NE * OUT_DIM];
__device__ __half g_b2h[(size_t)NE * OUT_DIM];

// ---------------- helpers ----------------
__device__ __forceinline__ float geluf(float x) {
    return 0.5f * x * (1.0f + erff(x * 0.70710678118654752f));
}
__device__ __forceinline__ uint32_t smem_u32(const void* p) {
    uint32_t a;
    asm("{ .reg .u64 t; cvta.to.shared.u64 t, %1; cvt.u32.u64 %0, t; }" : "=r"(a) : "l"(p));
    return a;
}
__device__ __forceinline__ uint4 pack8h(const float* v) {
    uint4 u;
    __half2 a = __floats2half2_rn(v[0], v[1]);
    __half2 b = __floats2half2_rn(v[2], v[3]);
    __half2 c = __floats2half2_rn(v[4], v[5]);
    __half2 d = __floats2half2_rn(v[6], v[7]);
    u.x = *(uint32_t*)&a; u.y = *(uint32_t*)&b;
    u.z = *(uint32_t*)&c; u.w = *(uint32_t*)&d;
    return u;
}
__device__ __forceinline__ void bulkcp(uint32_t dst, const void* src, uint32_t bytes, uint32_t mbar) {
    asm volatile(
        "cp.async.bulk.shared::cluster.global.mbarrier::complete_tx::bytes [%0], [%1], %2, [%3];"
        :: "r"(dst), "l"(src), "r"(bytes), "r"(mbar) : "memory");
}

#define MBAR_INIT(addr, cnt) \
    asm volatile("mbarrier.init.shared.b64 [%0], %1;" :: "r"(addr), "r"((uint32_t)(cnt)) : "memory")
#define MBAR_EXPECT(addr, n) \
    asm volatile("mbarrier.arrive.expect_tx.shared.b64 _, [%0], %1;" :: "r"(addr), "r"((uint32_t)(n)) : "memory")
#define MBAR_ARRIVE(addr) \
    asm volatile("mbarrier.arrive.shared.b64 _, [%0];" :: "r"(addr) : "memory")
#define MBAR_WAIT(addr, parity) do {                                              \
    uint32_t _m = (addr); uint32_t _p = (parity); uint32_t _d;                    \
    asm volatile("{\n\t.reg .pred p;\n\t"                                         \
        "mbarrier.try_wait.parity.acquire.cta.shared::cta.b64 p, [%1], %2;\n\t"   \
        "selp.b32 %0, 1, 0, p;\n\t}"                                              \
        : "=r"(_d) : "r"(_m), "r"(_p) : "memory");                                \
    if (!_d) {                                                                    \
        asm volatile("{\n\t.reg .pred P1;\n\t"                                    \
            "WAIT_LOOP_%=:\n\t"                                                   \
            "mbarrier.try_wait.parity.acquire.cta.shared::cta.b64 P1, [%0], %1, 0x989680;\n\t" \
            "@P1 bra.uni WAIT_DONE_%=;\n\t"                                       \
            "bra.uni WAIT_LOOP_%=;\n\t"                                           \
            "WAIT_DONE_%=:\n\t}"                                                  \
            :: "r"(_m), "r"(_p) : "memory");                                      \
    }                                                                             \
} while (0)

#define LDM4(r, addr)                                                            \
    asm volatile("ldmatrix.sync.aligned.m8n8.x4.shared.b16 {%0,%1,%2,%3}, [%4];" \
                 : "=r"((r)[0]), "=r"((r)[1]), "=r"((r)[2]), "=r"((r)[3])        \
                 : "r"(addr))

#define MMA16816(c, a, b0, b1)                                                   \
    asm volatile("mma.sync.aligned.m16n8k16.row.col.f32.f16.f16.f32 "            \
                 "{%0,%1,%2,%3}, {%4,%5,%6,%7}, {%8,%9}, {%0,%1,%2,%3};"         \
                 : "+f"((c)[0]), "+f"((c)[1]), "+f"((c)[2]), "+f"((c)[3])        \
                 : "r"((a)[0]), "r"((a)[1]), "r"((a)[2]), "r"((a)[3]),           \
                   "r"(b0), "r"(b1))

// ---------------- bulk-copy GEMM: C[e] = A @ Bt[e]^T + bias[e], fp16 out ----------------
// CTA 128x256, 512 threads (16 warps, 4M x 4N), warp tile 32x64.
// 64-k pipeline stages (A 16KB + B 32KB), 4-deep mbarrier ring; no syncthreads in loop.
// B fragments register-double-buffered across sub-blocks AND across stage boundaries:
// the full-wait for stage kt+1 is issued under stage kt's last MMA block.
#define A_T 16384
#define B_T 32768
#define STG (A_T + B_T)             // 49152
#define NST 4
#define SMEM_GEMM (256 + NST * STG) // 196864

template <bool FIRST>
__global__ void __launch_bounds__(512, 1) gemm_b(
    const uint4* __restrict__ Ap, const uint4* __restrict__ Bp,
    const float* __restrict__ bias, __half* __restrict__ C, const int ebase) {
    constexpr int KDIM = FIRST ? IN_DIM : HID_DIM;
    constexpr int NDIM = FIRST ? HID_DIM : OUT_DIM;
    constexpr int NKT = KDIM / 64;   // 64-k stages

    extern __shared__ char smem[];
    const uint32_t sb = smem_u32(smem);
    const uint32_t FULLB = sb, EMPTYB = sb + 64, TILES = sb + 256;

    const int tid = threadIdx.x, lane = tid & 31, wid = tid >> 5;
    const int mb = blockIdx.x, nb = blockIdx.y;
    const int e = ebase + blockIdx.z;

    if (tid == 0) {
#pragma unroll
        for (int s = 0; s < NST; s++) { MBAR_INIT(FULLB + 8 * s, 1); MBAR_INIT(EMPTYB + 8 * s, 16); }
    }
    __syncthreads();

    const uint4* Asrc = Ap + (size_t)(FIRST ? mb : (e * 64 + mb)) * (KDIM / 32) * 512;
    const uint4* Bsrc = Bp + (size_t)(e * (NDIM / 256) + nb) * (KDIM / 32) * 1024;

    auto fill = [&](int c) {
        const int s = c & (NST - 1);
        if (c >= NST) MBAR_WAIT(EMPTYB + 8 * s, (uint32_t)(((c / NST) - 1) & 1));
        MBAR_EXPECT(FULLB + 8 * s, STG);
        bulkcp(TILES + s * STG,       Asrc + (size_t)c * 1024, A_T, FULLB + 8 * s);
        bulkcp(TILES + s * STG + A_T, Bsrc + (size_t)c * 2048, B_T, FULLB + 8 * s);
    };

    if (tid == 0) { fill(0); fill(1); fill(2); }

    // fragment addressing (swizzle: quad ^= (row>>1)&3, rows are 64B within each 32-k chunk)
    const int wm = (wid >> 2) * 32, wn = (wid & 3) * 64;
    uint32_t aOff[2], aXs[2], bOff[4], bXs[4];
#pragma unroll
    for (int i = 0; i < 2; i++) {
        const int r = wm + (lane & 15) + 16 * i;
        aOff[i] = (uint32_t)(r * 64);
        aXs[i] = (uint32_t)(((r >> 1) & 3) << 4);
    }
#pragma unroll
    for (int t = 0; t < 4; t++) {
        const int r = wn + (lane & 15) + 16 * t;
        bOff[t] = (uint32_t)(r * 64);
        bXs[t] = (uint32_t)(((r >> 1) & 3) << 4);
    }
    const uint32_t qb = (uint32_t)((lane >> 4) << 4);

    float acc[2][8][4];
#pragma unroll
    for (int i = 0; i < 2; i++)
#pragma unroll
        for (int j = 0; j < 8; j++)
#pragma unroll
            for (int r = 0; r < 4; r++) acc[i][j][r] = 0.0f;

    uint32_t af[2][4], brA[4][4], brB[4][4];

    // prologue: wait for stage 0, preload its sub-0 B fragments
    MBAR_WAIT(FULLB, 0u);
#pragma unroll
    for (int t = 0; t < 4; t++) LDM4(brA[t], TILES + A_T + bOff[t] + (qb ^ bXs[t]));

    for (int kt = 0; kt < NKT; kt++) {
        if (tid == 0 && kt + NST - 1 < NKT) fill(kt + NST - 1);
        const uint32_t st = TILES + (uint32_t)(kt & (NST - 1)) * STG;

#pragma unroll
        for (int sub = 0; sub < 4; sub++) {
            const uint32_t ab = st + (uint32_t)(sub >> 1) * 8192;
            const uint32_t q  = qb + (uint32_t)(sub & 1) * 32;
            uint32_t (*cur)[4] = (sub & 1) ? brB : brA;
            uint32_t (*nxt)[4] = (sub & 1) ? brA : brB;
            // A frags for this sub
#pragma unroll
            for (int i = 0; i < 2; i++) LDM4(af[i], ab + aOff[i] + (q ^ aXs[i]));
            // prefetch B frags for the next sub (or for stage kt+1's sub 0)
            if (sub < 3) {
                const uint32_t bbn = st + A_T + (uint32_t)((sub + 1) >> 1) * 16384;
                const uint32_t qn  = qb + (uint32_t)((sub + 1) & 1) * 32;
#pragma unroll
                for (int t = 0; t < 4; t++) LDM4(nxt[t], bbn + bOff[t] + (qn ^ bXs[t]));
            } else if (kt + 1 < NKT) {
                MBAR_WAIT(FULLB + 8 * ((kt + 1) & (NST - 1)),
                          (uint32_t)(((kt + 1) / NST) & 1));
                const uint32_t stn = TILES + (uint32_t)((kt + 1) & (NST - 1)) * STG;
#pragma unroll
                for (int t = 0; t < 4; t++) LDM4(nxt[t], stn + A_T + bOff[t] + (qb ^ bXs[t]));
            }
#pragma unroll
            for (int i = 0; i < 2; i++)
#pragma unroll
                for (int j = 0; j < 8; j++) {
                    const int t = j >> 1;
                    const uint32_t b0 = (j & 1) ? cur[t][1] : cur[t][0];
                    const uint32_t b1 = (j & 1) ? cur[t][3] : cur[t][2];
                    MMA16816(acc[i][j], af[i], b0, b1);
                }
        }
        __syncwarp();
        if (lane == 0) MBAR_ARRIVE(EMPTYB + 8 * (kt & (NST - 1)));
    }

    // epilogue: bias add, fp16 store (row-major C)
    __half* Ce = C + (size_t)e * NTOK * NDIM;
    const int m0 = mb * 128, n0 = nb * 256;
    const int g = lane >> 2, tg = lane & 3;
#pragma unroll
    for (int i = 0; i < 2; i++) {
        const int row = m0 + wm + i * 16 + g;
#pragma unroll
        for (int j = 0; j < 8; j++) {
            const int col = n0 + wn + j * 8 + tg * 2;
            const float bv0 = bias[(size_t)e * NDIM + col];
            const float bv1 = bias[(size_t)e * NDIM + col + 1];
            *(__half2*)(Ce + (size_t)row * NDIM + col) =
                __floats2half2_rn(acc[i][j][0] + bv0, acc[i][j][1] + bv1);
            *(__half2*)(Ce + (size_t)(row + 8) * NDIM + col) =
                __floats2half2_rn(acc[i][j][2] + bv0, acc[i][j][3] + bv1);
        }
    }
}

// ---------------- weight pack: W [E][K][N] fp32 -> packed fp16 B-tiles ----------------
template <bool W1SEL>
__global__ void __launch_bounds__(256) pack_w(const float* __restrict__ W, int K, int N,
                                              const int ebase) {
    __shared__ __half sm[256][34];
    const int e = ebase + blockIdx.z, nb = blockIdx.x, kt = blockIdx.y;
    const int tid = threadIdx.x;
    const float* ip = W + ((size_t)e * K + (size_t)kt * 32) * N + (size_t)nb * 256;
#pragma unroll
    for (int kk = 0; kk < 32; kk++)
        sm[tid][kk] = __float2half_rn(ip[(size_t)kk * N + tid]);
    __syncthreads();
    uint4* op = W1SEL ? g_w1p : g_w2p;
    const size_t tb = ((size_t)(e * (N / 256) + nb) * (K / 32) + kt) * 1024;
    const uint32_t xr = (uint32_t)((tid >> 1) & 3);
#pragma unroll
    for (int q = 0; q < 4; q++) {
        uint4 u;
        const __half2* s2 = (const __half2*)&sm[tid][q * 8];
        u.x = *(const uint32_t*)&s2[0]; u.y = *(const uint32_t*)&s2[1];
        u.z = *(const uint32_t*)&s2[2]; u.w = *(const uint32_t*)&s2[3];
        op[tb + (size_t)tid * 4 + ((uint32_t)q ^ xr)] = u;
    }
}

// ---------------- x pack: fp32 [8192,1024] -> packed fp16 A-tiles ----------------
__global__ void __launch_bounds__(256) pack_x(const float* __restrict__ x) {
    const int mb = blockIdx.x, kt = blockIdx.y, tid = threadIdx.x;
    const int r = tid >> 1, h16 = tid & 1;
    const float* ip = x + (size_t)(mb * 128 + r) * 1024 + kt * 32 + h16 * 16;
    float v[16];
    *(float4*)(v)      = *(const float4*)(ip);
    *(float4*)(v + 4)  = *(const float4*)(ip + 4);
    *(float4*)(v + 8)  = *(const float4*)(ip + 8);
    *(float4*)(v + 12) = *(const float4*)(ip + 12);
    const size_t tb = ((size_t)mb * NKT1 + kt) * 512;
    const uint32_t xr = (uint32_t)((r >> 1) & 3);
    const uint32_t q0 = (uint32_t)(h16 * 2);
    g_xp[tb + (size_t)r * 4 + (q0 ^ xr)]       = pack8h(v);
    g_xp[tb + (size_t)r * 4 + ((q0 + 1) ^ xr)] = pack8h(v + 8);
}

// ---------------- fp32 -> fp16 convert (gamma/beta) ----------------
__global__ void conv_h(const float* __restrict__ src, __half* __restrict__ dst) {
    const int i = (blockIdx.x * 256 + threadIdx.x) * 4;
    float4 v = *(const float4*)(src + i);
    __half2* o = (__half2*)(dst + i);
    o[0] = __floats2half2_rn(v.x, v.y);
    o[1] = __floats2half2_rn(v.z, v.w);
}

// ------- LayerNorm + GELU: g_hh row-major -> g_hp packed A-tiles (per expert) -------
__global__ void __launch_bounds__(256) ln_gelu_kernel(const int e) {
    __shared__ float red[16];
    const int m = blockIdx.x;
    const __half* p = g_hh + ((size_t)e * NTOK + m) * HID_DIM;
    const int tid = threadIdx.x;

    float vals[16];
    float s = 0.f, s2 = 0.f;
    const __half2* ph = (const __half2*)(p + tid * 16);
#pragma unroll
    for (int i = 0; i < 8; i++) {
        float2 f = __half22float2(ph[i]);
        vals[2 * i] = f.x; vals[2 * i + 1] = f.y;
        s += f.x + f.y;
        s2 += f.x * f.x + f.y * f.y;
    }
#pragma unroll
    for (int o = 16; o > 0; o >>= 1) {
        s  += __shfl_xor_sync(0xffffffffu, s, o);
        s2 += __shfl_xor_sync(0xffffffffu, s2, o);
    }
    const int wi = tid >> 5, ln = tid & 31;
    if (ln == 0) { red[wi] = s; red[8 + wi] = s2; }
    __syncthreads();
    if (tid == 0) {
        float ts = 0.f, t2 = 0.f;
        for (int k = 0; k < 8; k++) { ts += red[k]; t2 += red[8 + k]; }
        red[0] = ts; red[8] = t2;
    }
    __syncthreads();
    const float invL = 1.0f / (float)HID_DIM;
    const float mean = red[0] * invL;
    const float inv = rsqrtf(red[8] * invL - mean * mean + 1e-5f);
    const __half2* gmp = (const __half2*)(g_g1h + (size_t)e * HID_DIM + tid * 16);
    const __half2* btp = (const __half2*)(g_b1h + (size_t)e * HID_DIM + tid * 16);
#pragma unroll
    for (int i = 0; i < 8; i++) {
        float2 gv = __half22float2(gmp[i]);
        float2 bv = __half22float2(btp[i]);
        vals[2 * i]     = geluf((vals[2 * i]     - mean) * inv * gv.x + bv.x);
        vals[2 * i + 1] = geluf((vals[2 * i + 1] - mean) * inv * gv.y + bv.y);
    }

    const int mb = m >> 7, r = m & 127, kt = tid >> 1;
    const uint32_t q0 = (uint32_t)((tid & 1) * 2);
    const uint32_t xr = (uint32_t)((r >> 1) & 3);
    const size_t tb = ((size_t)(e * 64 + mb) * NKT2 + kt) * 512;
    g_hp[tb + (size_t)r * 4 + (q0 ^ xr)]       = pack8h(vals);
    g_hp[tb + (size_t)r * 4 + ((q0 + 1) ^ xr)] = pack8h(vals + 8);
}

// -------- Final (4-expert half): LN(OUT) + GELU, weighted accumulate into out --------
__global__ void __launch_bounds__(256) final_kernel(
    const float* __restrict__ weights, float* __restrict__ out, const int ebase) {
    __shared__ float red[16];
    const int b = blockIdx.x;
    const int tid = threadIdx.x;
    const int wi = tid >> 5, ln = tid & 31;

    float accv[4] = {0.f, 0.f, 0.f, 0.f};
#pragma unroll 1
    for (int ee = 0; ee < 4; ee++) {
        const int e = ebase + ee;
        const __half* p = g_yh + ((size_t)e * NTOK + b) * OUT_DIM;
        float vals[4];
        float s = 0.f, s2 = 0.f;
#pragma unroll
        for (int r = 0; r < 4; r++) {
            float v = __half2float(p[tid + r * 256]);
            vals[r] = v;
            s += v; s2 += v * v;
        }
#pragma unroll
        for (int o = 16; o > 0; o >>= 1) {
            s  += __shfl_xor_sync(0xffffffffu, s, o);
            s2 += __shfl_xor_sync(0xffffffffu, s2, o);
        }
        if (ln == 0) { red[wi] = s; red[8 + wi] = s2; }
        __syncthreads();
        if (tid == 0) {
            float ts = 0.f, t2 = 0.f;
            for (int k = 0; k < 8; k++) { ts += red[k]; t2 += red[8 + k]; }
            red[0] = ts; red[8] = t2;
        }
        __syncthreads();
        const float invL = 1.0f / (float)OUT_DIM;
        const float mean = red[0] * invL;
        const float inv = rsqrtf(red[8] * invL - mean * mean + 1e-5f);
        const float w = weights[(size_t)b * NE + e];
#pragma unroll
        for (int r = 0; r < 4; r++) {
            const int i = tid + r * 256;
            const float gv = __half2float(g_g2h[(size_t)e * OUT_DIM + i]);
            const float bv = __half2float(g_b2h[(size_t)e * OUT_DIM + i]);
            const float v = (vals[r] - mean) * inv * gv + bv;
            accv[r] += w * geluf(v);
        }
        __syncthreads();
    }
#pragma unroll
    for (int r = 0; r < 4; r++) {
        const size_t oi = (size_t)b * OUT_DIM + tid + r * 256;
        out[oi] = (ebase == 0) ? accv[r] : (out[oi] + accv[r]);
    }
}

// ---------------- launch: three-stream fork/join pipeline (capture-safe) ----------------
extern "C" void kernel_launch(void* const* d_in, const int* in_sizes, int n_in,
                              void* d_out, int out_size) {
    const float* x   = (const float*)d_in[0];
    const float* wts = (const float*)d_in[1];
    const float* W1  = (const float*)d_in[2];
    const float* b1  = (const float*)d_in[3];
    const float* g1  = (const float*)d_in[4];
    const float* be1 = (const float*)d_in[5];
    const float* W2  = (const float*)d_in[6];
    const float* b2  = (const float*)d_in[7];
    const float* g2  = (const float*)d_in[8];
    const float* be2 = (const float*)d_in[9];
    float* out = (float*)d_out;

    cudaFuncSetAttribute(gemm_b<true>,  cudaFuncAttributeMaxDynamicSharedMemorySize, SMEM_GEMM);
    cudaFuncSetAttribute(gemm_b<false>, cudaFuncAttributeMaxDynamicSharedMemorySize, SMEM_GEMM);

    uint4* xp;  cudaGetSymbolAddress((void**)&xp,  g_xp);
    uint4* hp;  cudaGetSymbolAddress((void**)&hp,  g_hp);
    uint4* w1p; cudaGetSymbolAddress((void**)&w1p, g_w1p);
    uint4* w2p; cudaGetSymbolAddress((void**)&w2p, g_w2p);
    __half* hh; cudaGetSymbolAddress((void**)&hh,  g_hh);
    __half* yh; cudaGetSymbolAddress((void**)&yh,  g_yh);
    __half* g1h; cudaGetSymbolAddress((void**)&g1h, g_g1h);
    __half* b1h; cudaGetSymbolAddress((void**)&b1h, g_b1h);
    __half* g2h; cudaGetSymbolAddress((void**)&g2h, g_g2h);
    __half* b2h; cudaGetSymbolAddress((void**)&b2h, g_b2h);

    const cudaStream_t s0 = 0;
    static cudaStream_t s1 = nullptr, s2 = nullptr;
    if (!s1) {
        cudaStreamCreateWithFlags(&s1, cudaStreamNonBlocking);
        cudaStreamCreateWithFlags(&s2, cudaStreamNonBlocking);
    }
    auto mkev = []() {
        cudaEvent_t ev;
        cudaEventCreateWithFlags(&ev, cudaEventDisableTiming);
        return ev;
    };
    cudaEvent_t evFork = mkev(), evJoin1 = mkev(), evJoin2 = mkev();
    cudaEvent_t evPW1 = mkev(), evG2a = mkev(), evG2b = mkev();
    cudaEvent_t evG1[NE], evLN[NE];
    for (int e = 0; e < NE; e++) { evG1[e] = mkev(); evLN[e] = mkev(); }

    // fork s1, s2 from the default stream
    cudaEventRecord(evFork, s0);
    cudaStreamWaitEvent(s1, evFork, 0);
    cudaStreamWaitEvent(s2, evFork, 0);

    // s0 critical path: only what GEMM1(0) needs
    pack_x<<<dim3(64, NKT1), 256, 0, s0>>>(x);
    pack_w<true><<<dim3(HID_DIM / 256, NKT1, 1), 256, 0, s0>>>(W1, IN_DIM, HID_DIM, 0);

    // s1: the rest of prep
    pack_w<true><<<dim3(HID_DIM / 256, NKT1, NE - 1), 256, 0, s1>>>(W1, IN_DIM, HID_DIM, 1);
    cudaEventRecord(evPW1, s1);
    conv_h<<<(NE * HID_DIM) / 1024, 256, 0, s1>>>(g1, g1h);
    conv_h<<<(NE * HID_DIM) / 1024, 256, 0, s1>>>(be1, b1h);
    pack_w<false><<<dim3(OUT_DIM / 256, NKT2, NE), 256, 0, s1>>>(W2, HID_DIM, OUT_DIM, 0);
    conv_h<<<(NE * OUT_DIM) / 1024, 256, 0, s1>>>(g2, g2h);
    conv_h<<<(NE * OUT_DIM) / 1024, 256, 0, s1>>>(be2, b2h);

    // phase 1: GEMM1 per expert on s0; LN per expert on s1 overlapped with next GEMM1
    for (int e = 0; e < NE; e++) {
        if (e == 1) cudaStreamWaitEvent(s0, evPW1, 0);  // experts 1..7 packed on s1
        gemm_b<true><<<dim3(64, HID_DIM / 256, 1), 512, SMEM_GEMM, s0>>>(xp, w1p, b1, hh, e);
        cudaEventRecord(evG1[e], s0);
        cudaStreamWaitEvent(s1, evG1[e], 0);
        ln_gelu_kernel<<<NTOK, 256, 0, s1>>>(e);
        cudaEventRecord(evLN[e], s1);
    }

    // phase 2 on s2: GEMM2 halves start as soon as their LNs are done,
    // overlapping GEMM1(4..7) still running on s0.
    for (int e = 0; e < 4; e++) cudaStreamWaitEvent(s2, evLN[e], 0);
    gemm_b<false><<<dim3(64, OUT_DIM / 256, 4), 512, SMEM_GEMM, s2>>>(hp, w2p, b2, yh, 0);
    cudaEventRecord(evG2a, s2);
    for (int e = 4; e < NE; e++) cudaStreamWaitEvent(s2, evLN[e], 0);
    gemm_b<false><<<dim3(64, OUT_DIM / 256, 4), 512, SMEM_GEMM, s2>>>(hp, w2p, b2, yh, 4);
    cudaEventRecord(evG2b, s2);

    // final halves on s1 (in-stream order preserves out accumulate ordering)
    cudaStreamWaitEvent(s1, evG2a, 0);
    final_kernel<<<NTOK, 256, 0, s1>>>(wts, out, 0);
    cudaStreamWaitEvent(s1, evG2b, 0);
    final_kernel<<<NTOK, 256, 0, s1>>>(wts, out, 4);

    // join both side streams back into the default stream
    cudaEventRecord(evJoin1, s1);
    cudaEventRecord(evJoin2, s2);
    cudaStreamWaitEvent(s0, evJoin1, 0);
    cudaStreamWaitEvent(s0, evJoin2, 0);
}

// round 17
// speedup vs baseline: 1.0232x; 1.0047x over previous
#include <cuda_runtime.h>
#include <cuda_fp16.h>
#include <cstdint>
#include <cstddef>

#define NTOK 8192
#define IN_DIM 1024
#define HID_DIM 4096
#define OUT_DIM 1024
#define NE 8
#define NKT1 (IN_DIM / 32)   // 32-k chunks (packing granularity)
#define NKT2 (HID_DIM / 32)

// Packed tile buffers (uint4 units; per 32-k chunk: A-tile 128x32h = 8KB = 512 u4,
// B-tile 256x32h = 16KB = 1024 u4).
__device__ uint4 g_xp[(size_t)64 * NKT1 * 512];            // x packed: (mb, kt) 16MB
__device__ uint4 g_hp[(size_t)NE * 64 * NKT2 * 512];       // h packed: (e*64+mb, kt) 512MB
__device__ uint4 g_w1p[(size_t)NE * 16 * NKT1 * 1024];     // W1^T packed: (e,nb,kt) 64MB
__device__ uint4 g_w2p[(size_t)NE * 4 * NKT2 * 1024];      // W2^T packed 64MB
__device__ __half g_hh[(size_t)NE * NTOK * HID_DIM];       // GEMM1 out, row-major
__device__ __half g_yh[(size_t)NE * NTOK * OUT_DIM];       // GEMM2 out, row-major
// fp16 gamma/beta (exactly representable: ones/zeros)
__device__ __half g_g1h[(size_t)NE * HID_DIM];
__device__ __half g_b1h[(size_t)NE * HID_DIM];
__device__ __half g_g2h[(size_t)NE * OUT_DIM];
__device__ __half g_b2h[(size_t)NE * OUT_DIM];

// ---------------- helpers ----------------
__device__ __forceinline__ float geluf(float x) {
    return 0.5f * x * (1.0f + erff(x * 0.70710678118654752f));
}
__device__ __forceinline__ uint32_t smem_u32(const void* p) {
    uint32_t a;
    asm("{ .reg .u64 t; cvta.to.shared.u64 t, %1; cvt.u32.u64 %0, t; }" : "=r"(a) : "l"(p));
    return a;
}
__device__ __forceinline__ uint4 pack8h(const float* v) {
    uint4 u;
    __half2 a = __floats2half2_rn(v[0], v[1]);
    __half2 b = __floats2half2_rn(v[2], v[3]);
    __half2 c = __floats2half2_rn(v[4], v[5]);
    __half2 d = __floats2half2_rn(v[6], v[7]);
    u.x = *(uint32_t*)&a; u.y = *(uint32_t*)&b;
    u.z = *(uint32_t*)&c; u.w = *(uint32_t*)&d;
    return u;
}
__device__ __forceinline__ void bulkcp(uint32_t dst, const void* src, uint32_t bytes, uint32_t mbar) {
    asm volatile(
        "cp.async.bulk.shared::cluster.global.mbarrier::complete_tx::bytes [%0], [%1], %2, [%3];"
        :: "r"(dst), "l"(src), "r"(bytes), "r"(mbar) : "memory");
}

#define MBAR_INIT(addr, cnt) \
    asm volatile("mbarrier.init.shared.b64 [%0], %1;" :: "r"(addr), "r"((uint32_t)(cnt)) : "memory")
#define MBAR_EXPECT(addr, n) \
    asm volatile("mbarrier.arrive.expect_tx.shared.b64 _, [%0], %1;" :: "r"(addr), "r"((uint32_t)(n)) : "memory")
#define MBAR_ARRIVE(addr) \
    asm volatile("mbarrier.arrive.shared.b64 _, [%0];" :: "r"(addr) : "memory")
#define MBAR_WAIT(addr, parity) do {                                              \
    uint32_t _m = (addr); uint32_t _p = (parity); uint32_t _d;                    \
    asm volatile("{\n\t.reg .pred p;\n\t"                                         \
        "mbarrier.try_wait.parity.acquire.cta.shared::cta.b64 p, [%1], %2;\n\t"   \
        "selp.b32 %0, 1, 0, p;\n\t}"                                              \
        : "=r"(_d) : "r"(_m), "r"(_p) : "memory");                                \
    if (!_d) {                                                                    \
        asm volatile("{\n\t.reg .pred P1;\n\t"                                    \
            "WAIT_LOOP_%=:\n\t"                                                   \
            "mbarrier.try_wait.parity.acquire.cta.shared::cta.b64 P1, [%0], %1, 0x989680;\n\t" \
            "@P1 bra.uni WAIT_DONE_%=;\n\t"                                       \
            "bra.uni WAIT_LOOP_%=;\n\t"                                           \
            "WAIT_DONE_%=:\n\t}"                                                  \
            :: "r"(_m), "r"(_p) : "memory");                                      \
    }                                                                             \
} while (0)

#define LDM4(r, addr)                                                            \
    asm volatile("ldmatrix.sync.aligned.m8n8.x4.shared.b16 {%0,%1,%2,%3}, [%4];" \
                 : "=r"((r)[0]), "=r"((r)[1]), "=r"((r)[2]), "=r"((r)[3])        \
                 : "r"(addr))

#define MMA16816(c, a, b0, b1)                                                   \
    asm volatile("mma.sync.aligned.m16n8k16.row.col.f32.f16.f16.f32 "            \
                 "{%0,%1,%2,%3}, {%4,%5,%6,%7}, {%8,%9}, {%0,%1,%2,%3};"         \
                 : "+f"((c)[0]), "+f"((c)[1]), "+f"((c)[2]), "+f"((c)[3])        \
                 : "r"((a)[0]), "r"((a)[1]), "r"((a)[2]), "r"((a)[3]),           \
                   "r"(b0), "r"(b1))

// ---------------- bulk-copy GEMM: C[e] = A @ Bt[e]^T + bias[e], fp16 out ----------------
// CTA 128x256, 512 threads (16 warps, 4M x 4N), warp tile 32x64.
// 64-k pipeline stages (A 16KB + B 32KB), 4-deep mbarrier ring; no syncthreads in loop.
// B fragments register-double-buffered across sub-blocks AND across stage boundaries.
#define A_T 16384
#define B_T 32768
#define STG (A_T + B_T)             // 49152
#define NST 4
#define SMEM_GEMM (256 + NST * STG) // 196864

template <bool FIRST>
__global__ void __launch_bounds__(512, 1) gemm_b(
    const uint4* __restrict__ Ap, const uint4* __restrict__ Bp,
    const float* __restrict__ bias, __half* __restrict__ C, const int ebase) {
    constexpr int KDIM = FIRST ? IN_DIM : HID_DIM;
    constexpr int NDIM = FIRST ? HID_DIM : OUT_DIM;
    constexpr int NKT = KDIM / 64;   // 64-k stages

    extern __shared__ char smem[];
    const uint32_t sb = smem_u32(smem);
    const uint32_t FULLB = sb, EMPTYB = sb + 64, TILES = sb + 256;

    const int tid = threadIdx.x, lane = tid & 31, wid = tid >> 5;
    const int mb = blockIdx.x, nb = blockIdx.y;
    const int e = ebase + blockIdx.z;

    if (tid == 0) {
#pragma unroll
        for (int s = 0; s < NST; s++) { MBAR_INIT(FULLB + 8 * s, 1); MBAR_INIT(EMPTYB + 8 * s, 16); }
    }
    __syncthreads();

    const uint4* Asrc = Ap + (size_t)(FIRST ? mb : (e * 64 + mb)) * (KDIM / 32) * 512;
    const uint4* Bsrc = Bp + (size_t)(e * (NDIM / 256) + nb) * (KDIM / 32) * 1024;

    auto fill = [&](int c) {
        const int s = c & (NST - 1);
        if (c >= NST) MBAR_WAIT(EMPTYB + 8 * s, (uint32_t)(((c / NST) - 1) & 1));
        MBAR_EXPECT(FULLB + 8 * s, STG);
        bulkcp(TILES + s * STG,       Asrc + (size_t)c * 1024, A_T, FULLB + 8 * s);
        bulkcp(TILES + s * STG + A_T, Bsrc + (size_t)c * 2048, B_T, FULLB + 8 * s);
    };

    if (tid == 0) { fill(0); fill(1); fill(2); }

    // fragment addressing (swizzle: quad ^= (row>>1)&3, rows are 64B within each 32-k chunk)
    const int wm = (wid >> 2) * 32, wn = (wid & 3) * 64;
    uint32_t aOff[2], aXs[2], bOff[4], bXs[4];
#pragma unroll
    for (int i = 0; i < 2; i++) {
        const int r = wm + (lane & 15) + 16 * i;
        aOff[i] = (uint32_t)(r * 64);
        aXs[i] = (uint32_t)(((r >> 1) & 3) << 4);
    }
#pragma unroll
    for (int t = 0; t < 4; t++) {
        const int r = wn + (lane & 15) + 16 * t;
        bOff[t] = (uint32_t)(r * 64);
        bXs[t] = (uint32_t)(((r >> 1) & 3) << 4);
    }
    const uint32_t qb = (uint32_t)((lane >> 4) << 4);

    float acc[2][8][4];
#pragma unroll
    for (int i = 0; i < 2; i++)
#pragma unroll
        for (int j = 0; j < 8; j++)
#pragma unroll
            for (int r = 0; r < 4; r++) acc[i][j][r] = 0.0f;

    uint32_t af[2][4], brA[4][4], brB[4][4];

    // prologue: wait for stage 0, preload its sub-0 B fragments
    MBAR_WAIT(FULLB, 0u);
#pragma unroll
    for (int t = 0; t < 4; t++) LDM4(brA[t], TILES + A_T + bOff[t] + (qb ^ bXs[t]));

    for (int kt = 0; kt < NKT; kt++) {
        if (tid == 0 && kt + NST - 1 < NKT) fill(kt + NST - 1);
        const uint32_t st = TILES + (uint32_t)(kt & (NST - 1)) * STG;

#pragma unroll
        for (int sub = 0; sub < 4; sub++) {
            const uint32_t ab = st + (uint32_t)(sub >> 1) * 8192;
            const uint32_t q  = qb + (uint32_t)(sub & 1) * 32;
            uint32_t (*cur)[4] = (sub & 1) ? brB : brA;
            uint32_t (*nxt)[4] = (sub & 1) ? brA : brB;
            // A frags for this sub
#pragma unroll
            for (int i = 0; i < 2; i++) LDM4(af[i], ab + aOff[i] + (q ^ aXs[i]));
            // prefetch B frags for the next sub (or for stage kt+1's sub 0)
            if (sub < 3) {
                const uint32_t bbn = st + A_T + (uint32_t)((sub + 1) >> 1) * 16384;
                const uint32_t qn  = qb + (uint32_t)((sub + 1) & 1) * 32;
#pragma unroll
                for (int t = 0; t < 4; t++) LDM4(nxt[t], bbn + bOff[t] + (qn ^ bXs[t]));
            } else if (kt + 1 < NKT) {
                MBAR_WAIT(FULLB + 8 * ((kt + 1) & (NST - 1)),
                          (uint32_t)(((kt + 1) / NST) & 1));
                const uint32_t stn = TILES + (uint32_t)((kt + 1) & (NST - 1)) * STG;
#pragma unroll
                for (int t = 0; t < 4; t++) LDM4(nxt[t], stn + A_T + bOff[t] + (qb ^ bXs[t]));
            }
#pragma unroll
            for (int i = 0; i < 2; i++)
#pragma unroll
                for (int j = 0; j < 8; j++) {
                    const int t = j >> 1;
                    const uint32_t b0 = (j & 1) ? cur[t][1] : cur[t][0];
                    const uint32_t b1 = (j & 1) ? cur[t][3] : cur[t][2];
                    MMA16816(acc[i][j], af[i], b0, b1);
                }
        }
        __syncwarp();
        if (lane == 0) MBAR_ARRIVE(EMPTYB + 8 * (kt & (NST - 1)));
    }

    // epilogue: bias add (hoisted loads), fp16 store (row-major C)
    __half* Ce = C + (size_t)e * NTOK * NDIM;
    const int m0 = mb * 128, n0 = nb * 256;
    const int g = lane >> 2, tg = lane & 3;
    float bv[8][2];
#pragma unroll
    for (int j = 0; j < 8; j++) {
        const int col = n0 + wn + j * 8 + tg * 2;
        bv[j][0] = bias[(size_t)e * NDIM + col];
        bv[j][1] = bias[(size_t)e * NDIM + col + 1];
    }
#pragma unroll
    for (int i = 0; i < 2; i++) {
        const int row = m0 + wm + i * 16 + g;
#pragma unroll
        for (int j = 0; j < 8; j++) {
            const int col = n0 + wn + j * 8 + tg * 2;
            *(__half2*)(Ce + (size_t)row * NDIM + col) =
                __floats2half2_rn(acc[i][j][0] + bv[j][0], acc[i][j][1] + bv[j][1]);
            *(__half2*)(Ce + (size_t)(row + 8) * NDIM + col) =
                __floats2half2_rn(acc[i][j][2] + bv[j][0], acc[i][j][3] + bv[j][1]);
        }
    }
}

// ---------------- weight pack: W [E][K][N] fp32 -> packed fp16 B-tiles ----------------
template <bool W1SEL>
__global__ void __launch_bounds__(256) pack_w(const float* __restrict__ W, int K, int N,
                                              const int ebase) {
    __shared__ __half sm[256][34];
    const int e = ebase + blockIdx.z, nb = blockIdx.x, kt = blockIdx.y;
    const int tid = threadIdx.x;
    const float* ip = W + ((size_t)e * K + (size_t)kt * 32) * N + (size_t)nb * 256;
#pragma unroll
    for (int kk = 0; kk < 32; kk++)
        sm[tid][kk] = __float2half_rn(ip[(size_t)kk * N + tid]);
    __syncthreads();
    uint4* op = W1SEL ? g_w1p : g_w2p;
    const size_t tb = ((size_t)(e * (N / 256) + nb) * (K / 32) + kt) * 1024;
    const uint32_t xr = (uint32_t)((tid >> 1) & 3);
#pragma unroll
    for (int q = 0; q < 4; q++) {
        uint4 u;
        const __half2* s2 = (const __half2*)&sm[tid][q * 8];
        u.x = *(const uint32_t*)&s2[0]; u.y = *(const uint32_t*)&s2[1];
        u.z = *(const uint32_t*)&s2[2]; u.w = *(const uint32_t*)&s2[3];
        op[tb + (size_t)tid * 4 + ((uint32_t)q ^ xr)] = u;
    }
}

// ---------------- x pack: fp32 [8192,1024] -> packed fp16 A-tiles ----------------
__global__ void __launch_bounds__(256) pack_x(const float* __restrict__ x) {
    const int mb = blockIdx.x, kt = blockIdx.y, tid = threadIdx.x;
    const int r = tid >> 1, h16 = tid & 1;
    const float* ip = x + (size_t)(mb * 128 + r) * 1024 + kt * 32 + h16 * 16;
    float v[16];
    *(float4*)(v)      = *(const float4*)(ip);
    *(float4*)(v + 4)  = *(const float4*)(ip + 4);
    *(float4*)(v + 8)  = *(const float4*)(ip + 8);
    *(float4*)(v + 12) = *(const float4*)(ip + 12);
    const size_t tb = ((size_t)mb * NKT1 + kt) * 512;
    const uint32_t xr = (uint32_t)((r >> 1) & 3);
    const uint32_t q0 = (uint32_t)(h16 * 2);
    g_xp[tb + (size_t)r * 4 + (q0 ^ xr)]       = pack8h(v);
    g_xp[tb + (size_t)r * 4 + ((q0 + 1) ^ xr)] = pack8h(v + 8);
}

// ---------------- fp32 -> fp16 convert (gamma/beta) ----------------
__global__ void conv_h(const float* __restrict__ src, __half* __restrict__ dst) {
    const int i = (blockIdx.x * 256 + threadIdx.x) * 4;
    float4 v = *(const float4*)(src + i);
    __half2* o = (__half2*)(dst + i);
    o[0] = __floats2half2_rn(v.x, v.y);
    o[1] = __floats2half2_rn(v.z, v.w);
}

// ------- LayerNorm + GELU: g_hh row-major -> g_hp packed A-tiles (per expert) -------
__global__ void __launch_bounds__(256) ln_gelu_kernel(const int e) {
    __shared__ float red[16];
    const int m = blockIdx.x;
    const __half* p = g_hh + ((size_t)e * NTOK + m) * HID_DIM;
    const int tid = threadIdx.x;

    float vals[16];
    float s = 0.f, s2 = 0.f;
    const __half2* ph = (const __half2*)(p + tid * 16);
#pragma unroll
    for (int i = 0; i < 8; i++) {
        float2 f = __half22float2(ph[i]);
        vals[2 * i] = f.x; vals[2 * i + 1] = f.y;
        s += f.x + f.y;
        s2 += f.x * f.x + f.y * f.y;
    }
#pragma unroll
    for (int o = 16; o > 0; o >>= 1) {
        s  += __shfl_xor_sync(0xffffffffu, s, o);
        s2 += __shfl_xor_sync(0xffffffffu, s2, o);
    }
    const int wi = tid >> 5, ln = tid & 31;
    if (ln == 0) { red[wi] = s; red[8 + wi] = s2; }
    __syncthreads();
    if (tid == 0) {
        float ts = 0.f, t2 = 0.f;
        for (int k = 0; k < 8; k++) { ts += red[k]; t2 += red[8 + k]; }
        red[0] = ts; red[8] = t2;
    }
    __syncthreads();
    const float invL = 1.0f / (float)HID_DIM;
    const float mean = red[0] * invL;
    const float inv = rsqrtf(red[8] * invL - mean * mean + 1e-5f);
    const __half2* gmp = (const __half2*)(g_g1h + (size_t)e * HID_DIM + tid * 16);
    const __half2* btp = (const __half2*)(g_b1h + (size_t)e * HID_DIM + tid * 16);
#pragma unroll
    for (int i = 0; i < 8; i++) {
        float2 gv = __half22float2(gmp[i]);
        float2 bv = __half22float2(btp[i]);
        vals[2 * i]     = geluf((vals[2 * i]     - mean) * inv * gv.x + bv.x);
        vals[2 * i + 1] = geluf((vals[2 * i + 1] - mean) * inv * gv.y + bv.y);
    }

    const int mb = m >> 7, r = m & 127, kt = tid >> 1;
    const uint32_t q0 = (uint32_t)((tid & 1) * 2);
    const uint32_t xr = (uint32_t)((r >> 1) & 3);
    const size_t tb = ((size_t)(e * 64 + mb) * NKT2 + kt) * 512;
    g_hp[tb + (size_t)r * 4 + (q0 ^ xr)]       = pack8h(vals);
    g_hp[tb + (size_t)r * 4 + ((q0 + 1) ^ xr)] = pack8h(vals + 8);
}

// -------- Final (4-expert half): LN(OUT) + GELU, weighted accumulate into out --------
__global__ void __launch_bounds__(256) final_kernel(
    const float* __restrict__ weights, float* __restrict__ out, const int ebase) {
    __shared__ float red[16];
    const int b = blockIdx.x;
    const int tid = threadIdx.x;
    const int wi = tid >> 5, ln = tid & 31;

    float accv[4] = {0.f, 0.f, 0.f, 0.f};
#pragma unroll 1
    for (int ee = 0; ee < 4; ee++) {
        const int e = ebase + ee;
        const __half* p = g_yh + ((size_t)e * NTOK + b) * OUT_DIM;
        float vals[4];
        float s = 0.f, s2 = 0.f;
#pragma unroll
        for (int r = 0; r < 4; r++) {
            float v = __half2float(p[tid + r * 256]);
            vals[r] = v;
            s += v; s2 += v * v;
        }
#pragma unroll
        for (int o = 16; o > 0; o >>= 1) {
            s  += __shfl_xor_sync(0xffffffffu, s, o);
            s2 += __shfl_xor_sync(0xffffffffu, s2, o);
        }
        if (ln == 0) { red[wi] = s; red[8 + wi] = s2; }
        __syncthreads();
        if (tid == 0) {
            float ts = 0.f, t2 = 0.f;
            for (int k = 0; k < 8; k++) { ts += red[k]; t2 += red[8 + k]; }
            red[0] = ts; red[8] = t2;
        }
        __syncthreads();
        const float invL = 1.0f / (float)OUT_DIM;
        const float mean = red[0] * invL;
        const float inv = rsqrtf(red[8] * invL - mean * mean + 1e-5f);
        const float w = weights[(size_t)b * NE + e];
#pragma unroll
        for (int r = 0; r < 4; r++) {
            const int i = tid + r * 256;
            const float gv = __half2float(g_g2h[(size_t)e * OUT_DIM + i]);
            const float bv = __half2float(g_b2h[(size_t)e * OUT_DIM + i]);
            const float v = (vals[r] - mean) * inv * gv + bv;
            accv[r] += w * geluf(v);
        }
        __syncthreads();
    }
#pragma unroll
    for (int r = 0; r < 4; r++) {
        const size_t oi = (size_t)b * OUT_DIM + tid + r * 256;
        out[oi] = (ebase == 0) ? accv[r] : (out[oi] + accv[r]);
    }
}

// ---------------- launch: three-stream fork/join pipeline (capture-safe) ----------------
extern "C" void kernel_launch(void* const* d_in, const int* in_sizes, int n_in,
                              void* d_out, int out_size) {
    const float* x   = (const float*)d_in[0];
    const float* wts = (const float*)d_in[1];
    const float* W1  = (const float*)d_in[2];
    const float* b1  = (const float*)d_in[3];
    const float* g1  = (const float*)d_in[4];
    const float* be1 = (const float*)d_in[5];
    const float* W2  = (const float*)d_in[6];
    const float* b2  = (const float*)d_in[7];
    const float* g2  = (const float*)d_in[8];
    const float* be2 = (const float*)d_in[9];
    float* out = (float*)d_out;

    cudaFuncSetAttribute(gemm_b<true>,  cudaFuncAttributeMaxDynamicSharedMemorySize, SMEM_GEMM);
    cudaFuncSetAttribute(gemm_b<false>, cudaFuncAttributeMaxDynamicSharedMemorySize, SMEM_GEMM);

    uint4* xp;  cudaGetSymbolAddress((void**)&xp,  g_xp);
    uint4* hp;  cudaGetSymbolAddress((void**)&hp,  g_hp);
    uint4* w1p; cudaGetSymbolAddress((void**)&w1p, g_w1p);
    uint4* w2p; cudaGetSymbolAddress((void**)&w2p, g_w2p);
    __half* hh; cudaGetSymbolAddress((void**)&hh,  g_hh);
    __half* yh; cudaGetSymbolAddress((void**)&yh,  g_yh);
    __half* g1h; cudaGetSymbolAddress((void**)&g1h, g_g1h);
    __half* b1h; cudaGetSymbolAddress((void**)&b1h, g_b1h);
    __half* g2h; cudaGetSymbolAddress((void**)&g2h, g_g2h);
    __half* b2h; cudaGetSymbolAddress((void**)&b2h, g_b2h);

    const cudaStream_t s0 = 0;
    static cudaStream_t s1 = nullptr, s2 = nullptr;
    if (!s1) {
        cudaStreamCreateWithFlags(&s1, cudaStreamNonBlocking);
        cudaStreamCreateWithFlags(&s2, cudaStreamNonBlocking);
    }
    auto mkev = []() {
        cudaEvent_t ev;
        cudaEventCreateWithFlags(&ev, cudaEventDisableTiming);
        return ev;
    };
    cudaEvent_t evFork = mkev(), evJoin1 = mkev(), evJoin2 = mkev();
    cudaEvent_t evPW1 = mkev(), evG2a = mkev(), evG2b = mkev();
    cudaEvent_t evG1[4], evLNp[4];
    for (int p = 0; p < 4; p++) { evG1[p] = mkev(); evLNp[p] = mkev(); }

    // fork s1, s2 from the default stream
    cudaEventRecord(evFork, s0);
    cudaStreamWaitEvent(s1, evFork, 0);
    cudaStreamWaitEvent(s2, evFork, 0);

    // s0 critical path: only what GEMM1 pair 0 needs
    pack_x<<<dim3(64, NKT1), 256, 0, s0>>>(x);
    pack_w<true><<<dim3(HID_DIM / 256, NKT1, 2), 256, 0, s0>>>(W1, IN_DIM, HID_DIM, 0);

    // s1: the rest of prep
    pack_w<true><<<dim3(HID_DIM / 256, NKT1, NE - 2), 256, 0, s1>>>(W1, IN_DIM, HID_DIM, 2);
    cudaEventRecord(evPW1, s1);
    conv_h<<<(NE * HID_DIM) / 1024, 256, 0, s1>>>(g1, g1h);
    conv_h<<<(NE * HID_DIM) / 1024, 256, 0, s1>>>(be1, b1h);
    pack_w<false><<<dim3(OUT_DIM / 256, NKT2, NE), 256, 0, s1>>>(W2, HID_DIM, OUT_DIM, 0);
    conv_h<<<(NE * OUT_DIM) / 1024, 256, 0, s1>>>(g2, g2h);
    conv_h<<<(NE * OUT_DIM) / 1024, 256, 0, s1>>>(be2, b2h);

    // phase 1: GEMM1 in 4 expert-pairs on s0; LN per expert on s1 overlapped
    for (int p = 0; p < 4; p++) {
        if (p == 1) cudaStreamWaitEvent(s0, evPW1, 0);  // experts 2..7 packed on s1
        gemm_b<true><<<dim3(64, HID_DIM / 256, 2), 512, SMEM_GEMM, s0>>>(xp, w1p, b1, hh, 2 * p);
        cudaEventRecord(evG1[p], s0);
        cudaStreamWaitEvent(s1, evG1[p], 0);
        ln_gelu_kernel<<<NTOK, 256, 0, s1>>>(2 * p);
        ln_gelu_kernel<<<NTOK, 256, 0, s1>>>(2 * p + 1);
        cudaEventRecord(evLNp[p], s1);
    }

    // phase 2 on s2: GEMM2 halves start as soon as their LN pairs are done,
    // overlapping GEMM1 pairs still running on s0.
    cudaStreamWaitEvent(s2, evLNp[0], 0);
    cudaStreamWaitEvent(s2, evLNp[1], 0);
    gemm_b<false><<<dim3(64, OUT_DIM / 256, 4), 512, SMEM_GEMM, s2>>>(hp, w2p, b2, yh, 0);
    cudaEventRecord(evG2a, s2);
    cudaStreamWaitEvent(s2, evLNp[2], 0);
    cudaStreamWaitEvent(s2, evLNp[3], 0);
    gemm_b<false><<<dim3(64, OUT_DIM / 256, 4), 512, SMEM_GEMM, s2>>>(hp, w2p, b2, yh, 4);
    cudaEventRecord(evG2b, s2);

    // final halves on s1 (in-stream order preserves out accumulate ordering)
    cudaStreamWaitEvent(s1, evG2a, 0);
    final_kernel<<<NTOK, 256, 0, s1>>>(wts, out, 0);
    cudaStreamWaitEvent(s1, evG2b, 0);
    final_kernel<<<NTOK, 256, 0, s1>>>(wts, out, 4);

    // join both side streams back into the default stream
    cudaEventRecord(evJoin1, s1);
    cudaEventRecord(evJoin2, s2);
    cudaStreamWaitEvent(s0, evJoin1, 0);
    cudaStreamWaitEvent(s0, evJoin2, 0);
}